// round 2
// baseline (speedup 1.0000x reference)
#include <cuda_runtime.h>

#define DIM 768
#define HEADS 12
#define DH 64
#define INNER 768
#define BATCH 2
#define SEQ 1024
#define ROWS (BATCH*SEQ)      // 2048
#define NN (SEQ*SEQ)          // 1048576
#define BH (BATCH*HEADS)      // 24
#define SCALE 0.125f
#define LN_EPS 1e-5f

// ---------------- scratch (device globals; no allocation allowed) ----------
__device__ float g_xn[ROWS*DIM];
__device__ float g_q[BH*SEQ*DH];
__device__ float g_k[BH*SEQ*DH];
__device__ float g_v[BH*SEQ*DH];
__device__ float g_attn[(size_t)BH*NN];   // ~100 MB
__device__ float g_P[(size_t)BH*NN];      // ~100 MB
__device__ float g_O[ROWS*INNER];
__device__ float g_M[HEADS*HEADS];

// ---------------- LayerNorm ------------------------------------------------
__global__ __launch_bounds__(256) void ln_kernel(const float* __restrict__ x,
                                                 const float* __restrict__ gam,
                                                 const float* __restrict__ bet) {
    int row = blockIdx.x;
    const float* xr = x + (size_t)row * DIM;
    float vals[3];
    float s = 0.f, s2 = 0.f;
#pragma unroll
    for (int i = 0; i < 3; i++) {
        float v = xr[threadIdx.x + i * 256];
        vals[i] = v; s += v; s2 += v * v;
    }
    __shared__ float sh1[32], sh2[32];
#pragma unroll
    for (int o = 16; o > 0; o >>= 1) {
        s  += __shfl_down_sync(0xffffffffu, s,  o);
        s2 += __shfl_down_sync(0xffffffffu, s2, o);
    }
    int lane = threadIdx.x & 31, wid = threadIdx.x >> 5;
    if (lane == 0) { sh1[wid] = s; sh2[wid] = s2; }
    __syncthreads();
    if (wid == 0) {
        s  = (lane < 8) ? sh1[lane] : 0.f;
        s2 = (lane < 8) ? sh2[lane] : 0.f;
#pragma unroll
        for (int o = 4; o > 0; o >>= 1) {
            s  += __shfl_down_sync(0xffffffffu, s,  o);
            s2 += __shfl_down_sync(0xffffffffu, s2, o);
        }
        if (lane == 0) { sh1[0] = s; sh2[0] = s2; }
    }
    __syncthreads();
    float mean = sh1[0] * (1.f / DIM);
    float var  = sh2[0] * (1.f / DIM) - mean * mean;
    float rstd = rsqrtf(var + LN_EPS);
#pragma unroll
    for (int i = 0; i < 3; i++) {
        int c = threadIdx.x + i * 256;
        g_xn[(size_t)row * DIM + c] = (vals[i] - mean) * rstd * gam[c] + bet[c];
    }
}

// ---------------- M = (-0.5*theta) @ gnn_w  (12x12) ------------------------
__global__ void m_kernel(const float* __restrict__ theta, const float* __restrict__ w) {
    int t = threadIdx.x;
    if (t < HEADS * HEADS) {
        int i = t / HEADS, m = t % HEADS;
        float s = 0.f;
#pragma unroll
        for (int j = 0; j < HEADS; j++)
            s += (-0.5f * theta[i * HEADS + j]) * w[j * HEADS + m];
        g_M[t] = s;
    }
}

// ---------------- QKV GEMM: C[2048,2304] = xn @ Wqkv^T, scatter to heads ---
__global__ __launch_bounds__(256) void qkv_gemm(const float* __restrict__ W) {
    __shared__ float As[64][17];
    __shared__ float Bs[64][17];
    int tx = threadIdx.x & 15, ty = threadIdx.x >> 4;
    int row0 = blockIdx.y * 64, col0 = blockIdx.x * 64;
    float acc[4][4] = {};
    int lr = threadIdx.x >> 2;
    int lc = (threadIdx.x & 3) * 4;
    for (int k0 = 0; k0 < DIM; k0 += 16) {
        float4 a = *(const float4*)(g_xn + (size_t)(row0 + lr) * DIM + k0 + lc);
        float4 b = *(const float4*)(W    + (size_t)(col0 + lr) * DIM + k0 + lc);
        As[lr][lc] = a.x; As[lr][lc+1] = a.y; As[lr][lc+2] = a.z; As[lr][lc+3] = a.w;
        Bs[lr][lc] = b.x; Bs[lr][lc+1] = b.y; Bs[lr][lc+2] = b.z; Bs[lr][lc+3] = b.w;
        __syncthreads();
#pragma unroll
        for (int k = 0; k < 16; k++) {
            float ra[4], rb[4];
#pragma unroll
            for (int i = 0; i < 4; i++) ra[i] = As[ty * 4 + i][k];
#pragma unroll
            for (int j = 0; j < 4; j++) rb[j] = Bs[tx * 4 + j][k];
#pragma unroll
            for (int i = 0; i < 4; i++)
#pragma unroll
                for (int j = 0; j < 4; j++) acc[i][j] += ra[i] * rb[j];
        }
        __syncthreads();
    }
#pragma unroll
    for (int i = 0; i < 4; i++) {
        int gi = row0 + ty * 4 + i;
        int b = gi >> 10, n = gi & 1023;
#pragma unroll
        for (int j = 0; j < 4; j++) {
            int gj = col0 + tx * 4 + j;
            int which = gj / INNER;
            int r = gj - which * INNER;
            int h = r >> 6, d = r & 63;
            float* dst = (which == 0) ? g_q : (which == 1) ? g_k : g_v;
            dst[((size_t)(b * HEADS + h) * SEQ + n) * DH + d] = acc[i][j];
        }
    }
}

// ---------------- dots: S = scale * q @ k^T per (b,h) ----------------------
__global__ __launch_bounds__(256) void dots_gemm() {
    int bz = blockIdx.z;
    const float* A = g_q + (size_t)bz * SEQ * DH;
    const float* Bm = g_k + (size_t)bz * SEQ * DH;
    __shared__ float As[64][17];
    __shared__ float Bs[64][17];
    int tx = threadIdx.x & 15, ty = threadIdx.x >> 4;
    int row0 = blockIdx.y * 64, col0 = blockIdx.x * 64;
    float acc[4][4] = {};
    int lr = threadIdx.x >> 2;
    int lc = (threadIdx.x & 3) * 4;
    for (int k0 = 0; k0 < DH; k0 += 16) {
        float4 a = *(const float4*)(A  + (size_t)(row0 + lr) * DH + k0 + lc);
        float4 b = *(const float4*)(Bm + (size_t)(col0 + lr) * DH + k0 + lc);
        As[lr][lc] = a.x; As[lr][lc+1] = a.y; As[lr][lc+2] = a.z; As[lr][lc+3] = a.w;
        Bs[lr][lc] = b.x; Bs[lr][lc+1] = b.y; Bs[lr][lc+2] = b.z; Bs[lr][lc+3] = b.w;
        __syncthreads();
#pragma unroll
        for (int k = 0; k < 16; k++) {
            float ra[4], rb[4];
#pragma unroll
            for (int i = 0; i < 4; i++) ra[i] = As[ty * 4 + i][k];
#pragma unroll
            for (int j = 0; j < 4; j++) rb[j] = Bs[tx * 4 + j][k];
#pragma unroll
            for (int i = 0; i < 4; i++)
#pragma unroll
                for (int j = 0; j < 4; j++) acc[i][j] += ra[i] * rb[j];
        }
        __syncthreads();
    }
    float* C = g_attn + (size_t)bz * NN;
#pragma unroll
    for (int i = 0; i < 4; i++)
#pragma unroll
        for (int j = 0; j < 4; j++)
            C[(size_t)(row0 + ty * 4 + i) * SEQ + col0 + tx * 4 + j] = acc[i][j] * SCALE;
}

// ---------------- softmax over rows of g_attn ------------------------------
__global__ __launch_bounds__(256) void softmax_kernel() {
    size_t r = blockIdx.x;
    float* row = g_attn + r * SEQ;
    float v[4];
    float m = -1e30f;
#pragma unroll
    for (int i = 0; i < 4; i++) { v[i] = row[threadIdx.x + i * 256]; m = fmaxf(m, v[i]); }
    __shared__ float sh[32];
#pragma unroll
    for (int o = 16; o > 0; o >>= 1) m = fmaxf(m, __shfl_down_sync(0xffffffffu, m, o));
    int lane = threadIdx.x & 31, wid = threadIdx.x >> 5;
    if (lane == 0) sh[wid] = m;
    __syncthreads();
    if (wid == 0) {
        m = (lane < 8) ? sh[lane] : -1e30f;
#pragma unroll
        for (int o = 4; o > 0; o >>= 1) m = fmaxf(m, __shfl_down_sync(0xffffffffu, m, o));
        if (lane == 0) sh[0] = m;
    }
    __syncthreads();
    float M = sh[0];
    float s = 0.f;
#pragma unroll
    for (int i = 0; i < 4; i++) { v[i] = __expf(v[i] - M); s += v[i]; }
    __syncthreads();
#pragma unroll
    for (int o = 16; o > 0; o >>= 1) s += __shfl_down_sync(0xffffffffu, s, o);
    if (lane == 0) sh[wid] = s;
    __syncthreads();
    if (wid == 0) {
        s = (lane < 8) ? sh[lane] : 0.f;
#pragma unroll
        for (int o = 4; o > 0; o >>= 1) s += __shfl_down_sync(0xffffffffu, s, o);
        if (lane == 0) sh[0] = s;
    }
    __syncthreads();
    float inv = 1.f / sh[0];
#pragma unroll
    for (int i = 0; i < 4; i++) row[threadIdx.x + i * 256] = v[i] * inv;
}

// ---------------- head-mix: P = attn + relu(M @ attn_over_heads) -----------
__global__ __launch_bounds__(256) void mix_kernel() {
    __shared__ float Ms[HEADS * HEADS];
    if (threadIdx.x < HEADS * HEADS) Ms[threadIdx.x] = g_M[threadIdx.x];
    __syncthreads();
    int t = blockIdx.x * 256 + threadIdx.x;     // 0 .. BATCH*NN-1
    int b = t >> 20;
    int pos = t & (NN - 1);
    float a[HEADS];
#pragma unroll
    for (int j = 0; j < HEADS; j++)
        a[j] = g_attn[(size_t)(b * HEADS + j) * NN + pos];
#pragma unroll
    for (int h = 0; h < HEADS; h++) {
        float s = 0.f;
#pragma unroll
        for (int j = 0; j < HEADS; j++) s += Ms[h * HEADS + j] * a[j];
        g_P[(size_t)(b * HEADS + h) * NN + pos] = a[h] + fmaxf(s, 0.f);
    }
}

// ---------------- AV: O[b,h] = P[b,h] @ v[b,h]  (NN gemm, K=1024) ----------
__global__ __launch_bounds__(256) void av_gemm() {
    int bz = blockIdx.z;
    const float* A  = g_P + (size_t)bz * NN;
    const float* Bv = g_v + (size_t)bz * SEQ * DH;
    __shared__ float As[64][17];
    __shared__ float Bs[16][68];
    int tx = threadIdx.x & 15, ty = threadIdx.x >> 4;
    int row0 = blockIdx.y * 64;
    float acc[4][4] = {};
    int lrA = threadIdx.x >> 2,  lcA = (threadIdx.x & 3) * 4;
    int lrB = threadIdx.x >> 4,  lcB = (threadIdx.x & 15) * 4;
    for (int k0 = 0; k0 < SEQ; k0 += 16) {
        float4 a = *(const float4*)(A  + (size_t)(row0 + lrA) * SEQ + k0 + lcA);
        float4 b = *(const float4*)(Bv + (size_t)(k0 + lrB) * DH + lcB);
        As[lrA][lcA] = a.x; As[lrA][lcA+1] = a.y; As[lrA][lcA+2] = a.z; As[lrA][lcA+3] = a.w;
        Bs[lrB][lcB] = b.x; Bs[lrB][lcB+1] = b.y; Bs[lrB][lcB+2] = b.z; Bs[lrB][lcB+3] = b.w;
        __syncthreads();
#pragma unroll
        for (int k = 0; k < 16; k++) {
            float ra[4], rb[4];
#pragma unroll
            for (int i = 0; i < 4; i++) ra[i] = As[ty * 4 + i][k];
#pragma unroll
            for (int j = 0; j < 4; j++) rb[j] = Bs[k][tx * 4 + j];
#pragma unroll
            for (int i = 0; i < 4; i++)
#pragma unroll
                for (int j = 0; j < 4; j++) acc[i][j] += ra[i] * rb[j];
        }
        __syncthreads();
    }
    int b = bz / HEADS, h = bz % HEADS;
#pragma unroll
    for (int i = 0; i < 4; i++) {
        int n = row0 + ty * 4 + i;
#pragma unroll
        for (int j = 0; j < 4; j++) {
            int d = tx * 4 + j;
            g_O[(size_t)(b * SEQ + n) * INNER + h * DH + d] = acc[i][j];
        }
    }
}

// ---------------- out projection: Y = O @ Wout^T + b_out -------------------
__global__ __launch_bounds__(256) void proj_gemm(const float* __restrict__ W,
                                                 const float* __restrict__ bias,
                                                 float* __restrict__ out) {
    __shared__ float As[64][17];
    __shared__ float Bs[64][17];
    int tx = threadIdx.x & 15, ty = threadIdx.x >> 4;
    int row0 = blockIdx.y * 64, col0 = blockIdx.x * 64;
    float acc[4][4] = {};
    int lr = threadIdx.x >> 2;
    int lc = (threadIdx.x & 3) * 4;
    for (int k0 = 0; k0 < INNER; k0 += 16) {
        float4 a = *(const float4*)(g_O + (size_t)(row0 + lr) * INNER + k0 + lc);
        float4 b = *(const float4*)(W   + (size_t)(col0 + lr) * INNER + k0 + lc);
        As[lr][lc] = a.x; As[lr][lc+1] = a.y; As[lr][lc+2] = a.z; As[lr][lc+3] = a.w;
        Bs[lr][lc] = b.x; Bs[lr][lc+1] = b.y; Bs[lr][lc+2] = b.z; Bs[lr][lc+3] = b.w;
        __syncthreads();
#pragma unroll
        for (int k = 0; k < 16; k++) {
            float ra[4], rb[4];
#pragma unroll
            for (int i = 0; i < 4; i++) ra[i] = As[ty * 4 + i][k];
#pragma unroll
            for (int j = 0; j < 4; j++) rb[j] = Bs[tx * 4 + j][k];
#pragma unroll
            for (int i = 0; i < 4; i++)
#pragma unroll
                for (int j = 0; j < 4; j++) acc[i][j] += ra[i] * rb[j];
        }
        __syncthreads();
    }
#pragma unroll
    for (int i = 0; i < 4; i++) {
        int gi = row0 + ty * 4 + i;
#pragma unroll
        for (int j = 0; j < 4; j++) {
            int gj = col0 + tx * 4 + j;
            out[(size_t)gi * DIM + gj] = acc[i][j] + bias[gj];
        }
    }
}

// ---------------- launcher -------------------------------------------------
extern "C" void kernel_launch(void* const* d_in, const int* in_sizes, int n_in,
                              void* d_out, int out_size) {
    const float* x     = (const float*)d_in[0];
    const float* ln_g  = (const float*)d_in[1];
    const float* ln_b  = (const float*)d_in[2];
    const float* w_qkv = (const float*)d_in[3];
    const float* w_out = (const float*)d_in[4];
    const float* b_out = (const float*)d_in[5];
    const float* theta = (const float*)d_in[6];
    const float* gnn_w = (const float*)d_in[7];
    float* out = (float*)d_out;

    ln_kernel<<<ROWS, 256>>>(x, ln_g, ln_b);
    m_kernel<<<1, 160>>>(theta, gnn_w);
    qkv_gemm<<<dim3(36, 32), 256>>>(w_qkv);
    dots_gemm<<<dim3(16, 16, BH), 256>>>();
    softmax_kernel<<<BH * SEQ, 256>>>();
    mix_kernel<<<(BATCH * NN) / 256, 256>>>();
    av_gemm<<<dim3(1, 16, BH), 256>>>();
    proj_gemm<<<dim3(12, 32), 256>>>(w_out, b_out, out);
}

// round 6
// speedup vs baseline: 2.1396x; 2.1396x over previous
#include <cuda_runtime.h>
#include <cstdint>

#define DIM 768
#define HEADS 12
#define DH 64
#define INNER 768
#define BATCH 2
#define SEQ 1024
#define ROWS (BATCH*SEQ)      // 2048
#define NN (SEQ*SEQ)          // 1048576
#define BH (BATCH*HEADS)      // 24
#define SCALE 0.125f
#define LN_EPS 1e-5f
#define PAD 36                // smem row stride in floats (conflict-free frag loads)

// ---------------- scratch (device globals; no allocation allowed) ----------
__device__ float g_xn[ROWS*DIM];
__device__ float g_q[BH*SEQ*DH];
__device__ float g_k[BH*SEQ*DH];
__device__ float g_vt[BH*DH*SEQ];              // V transposed: [bh][d][n]
__device__ float g_attn[(size_t)BH*NN];        // exp(logits), unnormalized
__device__ float g_P[(size_t)BH*NN];
__device__ float g_psum[BH*SEQ*8];
__device__ float g_rinv[BH*SEQ];
__device__ float g_O[ROWS*INNER];
__device__ float g_M[HEADS*HEADS];

// ---------------- helpers --------------------------------------------------
__device__ __forceinline__ float to_tf32(float x) {
    float y;
    asm("cvt.rna.tf32.f32 %0, %1;" : "=f"(y) : "f"(x));
    return y;
}
__device__ __forceinline__ void mma_tf32(float* c, const uint32_t* a, const uint32_t* b) {
    asm volatile(
        "mma.sync.aligned.m16n8k8.row.col.f32.tf32.tf32.f32 "
        "{%0,%1,%2,%3}, {%4,%5,%6,%7}, {%8,%9}, {%0,%1,%2,%3};"
        : "+f"(c[0]), "+f"(c[1]), "+f"(c[2]), "+f"(c[3])
        : "r"(a[0]), "r"(a[1]), "r"(a[2]), "r"(a[3]), "r"(b[0]), "r"(b[1]));
}

// ---------------- tf32 mma GEMM core: D[128,BN] += A[128,K] @ B[BN,K]^T ----
// 8 warps. BN=128: warps 2x4, warp tile 64x32 (MT=4). BN=64: warps 4x2,
// warp tile 32x32 (MT=2). K-chunk = 32 floats (4 k-steps of 8).
// Fragment ownership (m16n8k8): g=lane>>2, t=lane&3.
//   c0:(row g,     col 2t)   c1:(row g,     col 2t+1)
//   c2:(row g+8,   col 2t)   c3:(row g+8,   col 2t+1)
template<int BN>
__device__ __forceinline__ void gemm_mma(float* Cacc,
                                         const float* __restrict__ A, int lda,
                                         const float* __restrict__ B, int ldb,
                                         int K, float* As, float* Bs) {
    constexpr int WC = BN / 32;        // warp cols
    constexpr int WR = 8 / WC;         // warp rows
    constexpr int WM = 128 / WR;       // warp tile M
    constexpr int MT = WM / 16;        // m16 tiles per warp
    constexpr int BTPR = 256 / BN;     // threads per B row
    constexpr int BFPT = 32 / BTPR;    // floats per thread per B row

    const int tid = threadIdx.x, wid = tid >> 5, lane = tid & 31;
    const int g = lane >> 2, t = lane & 3;
    const int wr = wid / WC, wc = wid % WC;
    const int wm0 = wr * WM, wn0 = wc * 32;
    const int arow = tid >> 1, ac0 = (tid & 1) * 16;
    const int brow = tid / BTPR, bc0 = (tid % BTPR) * BFPT;

    for (int kb = 0; kb < K; kb += 32) {
        __syncthreads();
#pragma unroll
        for (int i = 0; i < 4; i++) {
            float4 v = *(const float4*)(A + (size_t)arow * lda + kb + ac0 + i * 4);
            v.x = to_tf32(v.x); v.y = to_tf32(v.y); v.z = to_tf32(v.z); v.w = to_tf32(v.w);
            *(float4*)&As[arow * PAD + ac0 + i * 4] = v;
        }
#pragma unroll
        for (int i = 0; i < BFPT / 4; i++) {
            float4 v = *(const float4*)(B + (size_t)brow * ldb + kb + bc0 + i * 4);
            v.x = to_tf32(v.x); v.y = to_tf32(v.y); v.z = to_tf32(v.z); v.w = to_tf32(v.w);
            *(float4*)&Bs[brow * PAD + bc0 + i * 4] = v;
        }
        __syncthreads();
#pragma unroll
        for (int ks = 0; ks < 4; ks++) {
            const int kk = ks * 8 + t;
            uint32_t af[MT][4], bf[4][2];
#pragma unroll
            for (int mi = 0; mi < MT; mi++) {
                int r = wm0 + mi * 16 + g;
                af[mi][0] = __float_as_uint(As[r * PAD + kk]);
                af[mi][1] = __float_as_uint(As[(r + 8) * PAD + kk]);
                af[mi][2] = __float_as_uint(As[r * PAD + kk + 4]);
                af[mi][3] = __float_as_uint(As[(r + 8) * PAD + kk + 4]);
            }
#pragma unroll
            for (int ni = 0; ni < 4; ni++) {
                int r = wn0 + ni * 8 + g;
                bf[ni][0] = __float_as_uint(Bs[r * PAD + kk]);
                bf[ni][1] = __float_as_uint(Bs[r * PAD + kk + 4]);
            }
#pragma unroll
            for (int mi = 0; mi < MT; mi++)
#pragma unroll
                for (int ni = 0; ni < 4; ni++)
                    mma_tf32(&Cacc[(mi * 4 + ni) * 4], af[mi], bf[ni]);
        }
    }
    __syncthreads();
}

// ---------------- LayerNorm ------------------------------------------------
__global__ __launch_bounds__(256) void ln_kernel(const float* __restrict__ x,
                                                 const float* __restrict__ gam,
                                                 const float* __restrict__ bet) {
    int row = blockIdx.x;
    const float* xr = x + (size_t)row * DIM;
    float vals[3];
    float s = 0.f, s2 = 0.f;
#pragma unroll
    for (int i = 0; i < 3; i++) {
        float v = xr[threadIdx.x + i * 256];
        vals[i] = v; s += v; s2 += v * v;
    }
    __shared__ float sh1[32], sh2[32];
#pragma unroll
    for (int o = 16; o > 0; o >>= 1) {
        s  += __shfl_down_sync(0xffffffffu, s,  o);
        s2 += __shfl_down_sync(0xffffffffu, s2, o);
    }
    int lane = threadIdx.x & 31, wid = threadIdx.x >> 5;
    if (lane == 0) { sh1[wid] = s; sh2[wid] = s2; }
    __syncthreads();
    if (wid == 0) {
        s  = (lane < 8) ? sh1[lane] : 0.f;
        s2 = (lane < 8) ? sh2[lane] : 0.f;
#pragma unroll
        for (int o = 4; o > 0; o >>= 1) {
            s  += __shfl_down_sync(0xffffffffu, s,  o);
            s2 += __shfl_down_sync(0xffffffffu, s2, o);
        }
        if (lane == 0) { sh1[0] = s; sh2[0] = s2; }
    }
    __syncthreads();
    float mean = sh1[0] * (1.f / DIM);
    float var  = sh2[0] * (1.f / DIM) - mean * mean;
    float rstd = rsqrtf(var + LN_EPS);
#pragma unroll
    for (int i = 0; i < 3; i++) {
        int c = threadIdx.x + i * 256;
        g_xn[(size_t)row * DIM + c] = (vals[i] - mean) * rstd * gam[c] + bet[c];
    }
}

// ---------------- M = (-0.5*theta) @ gnn_w ---------------------------------
__global__ void m_kernel(const float* __restrict__ theta, const float* __restrict__ w) {
    int t = threadIdx.x;
    if (t < HEADS * HEADS) {
        int i = t / HEADS, m = t % HEADS;
        float s = 0.f;
#pragma unroll
        for (int j = 0; j < HEADS; j++)
            s += (-0.5f * theta[i * HEADS + j]) * w[j * HEADS + m];
        g_M[t] = s;
    }
}

// ---------------- QKV: [2048,768] @ Wqkv^T[768,2304], scatter to heads -----
__global__ __launch_bounds__(256) void qkv_tc(const float* __restrict__ W) {
    __shared__ float As[128 * PAD];
    __shared__ float Bs[128 * PAD];
    int nb = blockIdx.x, mb = blockIdx.y;
    float Cacc[64] = {};
    gemm_mma<128>(Cacc, g_xn + (size_t)mb * 128 * DIM, DIM,
                  W + (size_t)nb * 128 * DIM, DIM, DIM, As, Bs);

    const int lane = threadIdx.x & 31, wid = threadIdx.x >> 5;
    const int g = lane >> 2, t = lane & 3;
    const int wr = wid >> 2, wc = wid & 3;
#pragma unroll
    for (int mi = 0; mi < 4; mi++) {
        int gi0 = mb * 128 + wr * 64 + mi * 16 + g;
#pragma unroll
        for (int ni = 0; ni < 4; ni++) {
            int j = nb * 128 + wc * 32 + ni * 8 + 2 * t;
            int which = j / INNER;
            int rc = j - which * INNER;
            int h = rc >> 6, d = rc & 63;
            const float* cp = &Cacc[(mi * 4 + ni) * 4];
#pragma unroll
            for (int half = 0; half < 2; half++) {
                int gi = gi0 + half * 8;
                int b = gi >> 10, n = gi & 1023;
                float c0 = cp[half * 2], c1 = cp[half * 2 + 1];
                if (which < 2) {
                    float* dst = (which == 0) ? g_q : g_k;
                    *(float2*)(dst + ((size_t)(b * HEADS + h) * SEQ + n) * DH + d)
                        = make_float2(c0, c1);
                } else {
                    float* p = g_vt + (size_t)(b * HEADS + h) * DH * SEQ + n;
                    p[(size_t)d * SEQ] = c0;
                    p[(size_t)(d + 1) * SEQ] = c1;
                }
            }
        }
    }
}

// ---------------- dots: exp(scale * q@k^T), partial row sums ---------------
__global__ __launch_bounds__(256) void dots_tc() {
    __shared__ float As[128 * PAD];
    __shared__ float Bs[128 * PAD];
    __shared__ float sred[128][4];
    int nb = blockIdx.x, mb = blockIdx.y, bz = blockIdx.z;
    float Cacc[64] = {};
    gemm_mma<128>(Cacc, g_q + (size_t)bz * SEQ * DH + (size_t)mb * 128 * DH, DH,
                  g_k + (size_t)bz * SEQ * DH + (size_t)nb * 128 * DH, DH, DH, As, Bs);

    const int lane = threadIdx.x & 31, wid = threadIdx.x >> 5;
    const int g = lane >> 2, t = lane & 3;
    const int wr = wid >> 2, wc = wid & 3;
    float rs0[4] = {}, rs1[4] = {};
#pragma unroll
    for (int mi = 0; mi < 4; mi++) {
        int row0 = mb * 128 + wr * 64 + mi * 16 + g;
#pragma unroll
        for (int ni = 0; ni < 4; ni++) {
            int col = nb * 128 + wc * 32 + ni * 8 + 2 * t;
            float* cp = &Cacc[(mi * 4 + ni) * 4];
            float e0 = __expf(cp[0] * SCALE), e1 = __expf(cp[1] * SCALE);
            float e2 = __expf(cp[2] * SCALE), e3 = __expf(cp[3] * SCALE);
            rs0[mi] += e0 + e1; rs1[mi] += e2 + e3;
            *(float2*)(g_attn + (size_t)bz * NN + (size_t)row0 * SEQ + col)
                = make_float2(e0, e1);
            *(float2*)(g_attn + (size_t)bz * NN + (size_t)(row0 + 8) * SEQ + col)
                = make_float2(e2, e3);
        }
    }
#pragma unroll
    for (int mi = 0; mi < 4; mi++) {
#pragma unroll
        for (int o = 1; o < 4; o <<= 1) {
            rs0[mi] += __shfl_xor_sync(0xffffffffu, rs0[mi], o);
            rs1[mi] += __shfl_xor_sync(0xffffffffu, rs1[mi], o);
        }
        if (t == 0) {
            int rl = wr * 64 + mi * 16 + g;
            sred[rl][wc] = rs0[mi];
            sred[rl + 8][wc] = rs1[mi];
        }
    }
    __syncthreads();
    if (threadIdx.x < 128) {
        float s = sred[threadIdx.x][0] + sred[threadIdx.x][1]
                + sred[threadIdx.x][2] + sred[threadIdx.x][3];
        g_psum[((size_t)bz * SEQ + mb * 128 + threadIdx.x) * 8 + nb] = s;
    }
}

// ---------------- 1/rowsum -------------------------------------------------
__global__ __launch_bounds__(256) void rinv_kernel() {
    int t = blockIdx.x * 256 + threadIdx.x;
    if (t < BH * SEQ) {
        float s = 0.f;
#pragma unroll
        for (int i = 0; i < 8; i++) s += g_psum[(size_t)t * 8 + i];
        g_rinv[t] = 1.f / s;
    }
}

// ---------------- head-mix: P = a + relu(M @ a), a normalized --------------
__global__ __launch_bounds__(256) void mix_kernel() {
    __shared__ float Ms[HEADS * HEADS];
    __shared__ float ri[HEADS];
    int t = blockIdx.x * 256 + threadIdx.x;
    int b = t >> 20;
    int pos = t & (NN - 1);
    int row = pos >> 10;
    if (threadIdx.x < HEADS * HEADS) Ms[threadIdx.x] = g_M[threadIdx.x];
    if (threadIdx.x < HEADS)
        ri[threadIdx.x] = g_rinv[(b * HEADS + threadIdx.x) * SEQ + row];
    __syncthreads();
    float a[HEADS];
#pragma unroll
    for (int j = 0; j < HEADS; j++)
        a[j] = g_attn[(size_t)(b * HEADS + j) * NN + pos] * ri[j];
#pragma unroll
    for (int h = 0; h < HEADS; h++) {
        float s = 0.f;
#pragma unroll
        for (int j = 0; j < HEADS; j++) s += Ms[h * HEADS + j] * a[j];
        g_P[(size_t)(b * HEADS + h) * NN + pos] = a[h] + fmaxf(s, 0.f);
    }
}

// ---------------- AV: O[n,d] = P[n,:] @ Vt[d,:]^T --------------------------
__global__ __launch_bounds__(256) void av_tc() {
    __shared__ float As[128 * PAD];
    __shared__ float Bs[64 * PAD];
    int mb = blockIdx.x, bz = blockIdx.y;
    float Cacc[32] = {};
    gemm_mma<64>(Cacc, g_P + (size_t)bz * NN + (size_t)mb * 128 * SEQ, SEQ,
                 g_vt + (size_t)bz * DH * SEQ, SEQ, SEQ, As, Bs);

    const int lane = threadIdx.x & 31, wid = threadIdx.x >> 5;
    const int g = lane >> 2, t = lane & 3;
    const int wr = wid >> 1, wc = wid & 1;
    int b = bz / HEADS, h = bz % HEADS;
#pragma unroll
    for (int mi = 0; mi < 2; mi++) {
        int n0 = mb * 128 + wr * 32 + mi * 16 + g;
#pragma unroll
        for (int ni = 0; ni < 4; ni++) {
            int d = wc * 32 + ni * 8 + 2 * t;
            float* cp = &Cacc[(mi * 4 + ni) * 4];
            *(float2*)(g_O + (size_t)(b * SEQ + n0) * INNER + h * DH + d)
                = make_float2(cp[0], cp[1]);
            *(float2*)(g_O + (size_t)(b * SEQ + n0 + 8) * INNER + h * DH + d)
                = make_float2(cp[2], cp[3]);
        }
    }
}

// ---------------- out projection -------------------------------------------
__global__ __launch_bounds__(256) void proj_tc(const float* __restrict__ W,
                                               const float* __restrict__ bias,
                                               float* __restrict__ out) {
    __shared__ float As[128 * PAD];
    __shared__ float Bs[128 * PAD];
    int nb = blockIdx.x, mb = blockIdx.y;
    float Cacc[64] = {};
    gemm_mma<128>(Cacc, g_O + (size_t)mb * 128 * INNER, INNER,
                  W + (size_t)nb * 128 * INNER, INNER, INNER, As, Bs);

    const int lane = threadIdx.x & 31, wid = threadIdx.x >> 5;
    const int g = lane >> 2, t = lane & 3;
    const int wr = wid >> 2, wc = wid & 3;
#pragma unroll
    for (int mi = 0; mi < 4; mi++) {
        int gi = mb * 128 + wr * 64 + mi * 16 + g;
#pragma unroll
        for (int ni = 0; ni < 4; ni++) {
            int j = nb * 128 + wc * 32 + ni * 8 + 2 * t;
            float b0 = bias[j], b1 = bias[j + 1];
            float* cp = &Cacc[(mi * 4 + ni) * 4];
            *(float2*)(out + (size_t)gi * DIM + j) = make_float2(cp[0] + b0, cp[1] + b1);
            *(float2*)(out + (size_t)(gi + 8) * DIM + j) = make_float2(cp[2] + b0, cp[3] + b1);
        }
    }
}

// ---------------- launcher -------------------------------------------------
extern "C" void kernel_launch(void* const* d_in, const int* in_sizes, int n_in,
                              void* d_out, int out_size) {
    const float* x     = (const float*)d_in[0];
    const float* ln_g  = (const float*)d_in[1];
    const float* ln_b  = (const float*)d_in[2];
    const float* w_qkv = (const float*)d_in[3];
    const float* w_out = (const float*)d_in[4];
    const float* b_out = (const float*)d_in[5];
    const float* theta = (const float*)d_in[6];
    const float* gnn_w = (const float*)d_in[7];
    float* out = (float*)d_out;

    ln_kernel<<<ROWS, 256>>>(x, ln_g, ln_b);
    m_kernel<<<1, 160>>>(theta, gnn_w);
    qkv_tc<<<dim3(18, 16), 256>>>(w_qkv);
    dots_tc<<<dim3(8, 8, BH), 256>>>();
    rinv_kernel<<<96, 256>>>();
    mix_kernel<<<(BATCH * NN) / 256, 256>>>();
    av_tc<<<dim3(8, BH), 256>>>();
    proj_tc<<<dim3(6, 16), 256>>>(w_out, b_out, out);
}

// round 7
// speedup vs baseline: 2.3486x; 1.0977x over previous
#include <cuda_runtime.h>
#include <cstdint>

#define DIM 768
#define HEADS 12
#define DH 64
#define INNER 768
#define BATCH 2
#define SEQ 1024
#define ROWS (BATCH*SEQ)      // 2048
#define NN (SEQ*SEQ)          // 1048576
#define BH (BATCH*HEADS)      // 24
#define SCALE 0.125f
#define LN_EPS 1e-5f
#define PADC 36               // floats per 32-float chunk row (144B, 16B mult)

// ---------------- scratch (device globals; no allocation allowed) ----------
__device__ float g_xn[ROWS*DIM];
__device__ float g_q[BH*SEQ*DH];
__device__ float g_k[BH*SEQ*DH];
__device__ float g_vt[BH*DH*SEQ];              // V transposed: [bh][d][n]
__device__ float g_attn[(size_t)BH*NN];        // exp(logits), unnormalized
__device__ float g_P[(size_t)BH*NN];
__device__ float g_psum[BH*SEQ*8];
__device__ float g_O[ROWS*INNER];
__device__ float g_M[HEADS*HEADS];

// ---------------- helpers --------------------------------------------------
__device__ __forceinline__ uint32_t smem_u32(const void* p) {
    uint32_t a;
    asm("{ .reg .u64 t; cvta.to.shared.u64 t, %1; cvt.u32.u64 %0, t; }"
        : "=r"(a) : "l"(p));
    return a;
}
__device__ __forceinline__ float to_tf32(float x) {
    float y;
    asm("cvt.rna.tf32.f32 %0, %1;" : "=f"(y) : "f"(x));
    return y;
}
__device__ __forceinline__ void mma_tf32(float* c, const uint32_t* a, const uint32_t* b) {
    asm volatile(
        "mma.sync.aligned.m16n8k8.row.col.f32.tf32.tf32.f32 "
        "{%0,%1,%2,%3}, {%4,%5,%6,%7}, {%8,%9}, {%0,%1,%2,%3};"
        : "+f"(c[0]), "+f"(c[1]), "+f"(c[2]), "+f"(c[3])
        : "r"(a[0]), "r"(a[1]), "r"(a[2]), "r"(a[3]), "r"(b[0]), "r"(b[1]));
}
#define CP_ASYNC16(dst, src) \
    asm volatile("cp.async.cg.shared.global [%0], [%1], 16;" \
        :: "r"(dst), "l"(src) : "memory")
#define CP_COMMIT()  asm volatile("cp.async.commit_group;" ::: "memory")
#define CP_WAIT1()   asm volatile("cp.async.wait_group 1;" ::: "memory")
#define CP_WAIT0()   asm volatile("cp.async.wait_group 0;" ::: "memory")

// ---- pipelined tf32 mma core: D[128,BN] += A[128,K] @ B[BN,K]^T -----------
// 8 warps. BN=128: warps 2x4, warp tile 64x32 (MT=4). BN=64: warps 4x2,
// warp tile 32x32 (MT=2). K processed in 32-float chunks, cp.async
// double-buffered. tf32 rna conversion at fragment-load time.
// dynamic smem: As[2][128*PADC] then Bs[2][BN*PADC].
template<int BN>
__device__ __forceinline__ void gemm_pipe(float* Cacc,
                                          const float* __restrict__ A, int lda,
                                          const float* __restrict__ B, int ldb,
                                          int K, float* As, float* Bs) {
    constexpr int WC = BN / 32;
    constexpr int WR = 8 / WC;
    constexpr int WM = 128 / WR;
    constexpr int MT = WM / 16;
    constexpr int BTPR = 256 / BN;     // threads per B row
    constexpr int BSEG = 32 / BTPR;    // floats per thread (16 or 8)

    const int tid = threadIdx.x, wid = tid >> 5, lane = tid & 31;
    const int g = lane >> 2, t = lane & 3;
    const int wr = wid / WC, wc = wid % WC;
    const int wm0 = wr * WM, wn0 = wc * 32;
    const int arow = tid >> 1, ac0 = (tid & 1) * 16;
    const int brow = tid / BTPR, bc0 = (tid % BTPR) * BSEG;

    const uint32_t sa = smem_u32(As);
    const uint32_t sb = smem_u32(Bs);
    const int nch = K >> 5;

    auto prefetch = [&](int c, int buf) {
        const float* ap = A + (size_t)arow * lda + c * 32 + ac0;
        uint32_t da = sa + (uint32_t)(buf * 128 * PADC + arow * PADC + ac0) * 4u;
#pragma unroll
        for (int i = 0; i < 4; i++) CP_ASYNC16(da + i * 16, ap + i * 4);
        const float* bp = B + (size_t)brow * ldb + c * 32 + bc0;
        uint32_t db = sb + (uint32_t)(buf * BN * PADC + brow * PADC + bc0) * 4u;
#pragma unroll
        for (int i = 0; i < BSEG / 4; i++) CP_ASYNC16(db + i * 16, bp + i * 4);
        CP_COMMIT();
    };

    prefetch(0, 0);
    for (int c = 0; c < nch; c++) {
        if (c + 1 < nch) { prefetch(c + 1, (c + 1) & 1); CP_WAIT1(); }
        else             { CP_WAIT0(); }
        __syncthreads();
        const float* Ab = As + (c & 1) * 128 * PADC;
        const float* Bb = Bs + (c & 1) * BN * PADC;
#pragma unroll
        for (int ks = 0; ks < 4; ks++) {
            const int kk = ks * 8 + t;
            uint32_t af[MT][4], bf[4][2];
#pragma unroll
            for (int mi = 0; mi < MT; mi++) {
                int r = wm0 + mi * 16 + g;
                af[mi][0] = __float_as_uint(to_tf32(Ab[r * PADC + kk]));
                af[mi][1] = __float_as_uint(to_tf32(Ab[(r + 8) * PADC + kk]));
                af[mi][2] = __float_as_uint(to_tf32(Ab[r * PADC + kk + 4]));
                af[mi][3] = __float_as_uint(to_tf32(Ab[(r + 8) * PADC + kk + 4]));
            }
#pragma unroll
            for (int ni = 0; ni < 4; ni++) {
                int r = wn0 + ni * 8 + g;
                bf[ni][0] = __float_as_uint(to_tf32(Bb[r * PADC + kk]));
                bf[ni][1] = __float_as_uint(to_tf32(Bb[r * PADC + kk + 4]));
            }
#pragma unroll
            for (int mi = 0; mi < MT; mi++)
#pragma unroll
                for (int ni = 0; ni < 4; ni++)
                    mma_tf32(&Cacc[(mi * 4 + ni) * 4], af[mi], bf[ni]);
        }
        __syncthreads();
    }
}

#define SMEM128 ((2*128 + 2*128) * PADC * 4)   // 73728 B
#define SMEM64  ((2*128 + 2*64)  * PADC * 4)   // 55296 B

// ---------------- LayerNorm ------------------------------------------------
__global__ __launch_bounds__(256) void ln_kernel(const float* __restrict__ x,
                                                 const float* __restrict__ gam,
                                                 const float* __restrict__ bet) {
    int row = blockIdx.x;
    const float* xr = x + (size_t)row * DIM;
    float vals[3];
    float s = 0.f, s2 = 0.f;
#pragma unroll
    for (int i = 0; i < 3; i++) {
        float v = xr[threadIdx.x + i * 256];
        vals[i] = v; s += v; s2 += v * v;
    }
    __shared__ float sh1[32], sh2[32];
#pragma unroll
    for (int o = 16; o > 0; o >>= 1) {
        s  += __shfl_down_sync(0xffffffffu, s,  o);
        s2 += __shfl_down_sync(0xffffffffu, s2, o);
    }
    int lane = threadIdx.x & 31, wid = threadIdx.x >> 5;
    if (lane == 0) { sh1[wid] = s; sh2[wid] = s2; }
    __syncthreads();
    if (wid == 0) {
        s  = (lane < 8) ? sh1[lane] : 0.f;
        s2 = (lane < 8) ? sh2[lane] : 0.f;
#pragma unroll
        for (int o = 4; o > 0; o >>= 1) {
            s  += __shfl_down_sync(0xffffffffu, s,  o);
            s2 += __shfl_down_sync(0xffffffffu, s2, o);
        }
        if (lane == 0) { sh1[0] = s; sh2[0] = s2; }
    }
    __syncthreads();
    float mean = sh1[0] * (1.f / DIM);
    float var  = sh2[0] * (1.f / DIM) - mean * mean;
    float rstd = rsqrtf(var + LN_EPS);
#pragma unroll
    for (int i = 0; i < 3; i++) {
        int c = threadIdx.x + i * 256;
        g_xn[(size_t)row * DIM + c] = (vals[i] - mean) * rstd * gam[c] + bet[c];
    }
}

// ---------------- M = (-0.5*theta) @ gnn_w ---------------------------------
__global__ void m_kernel(const float* __restrict__ theta, const float* __restrict__ w) {
    int t = threadIdx.x;
    if (t < HEADS * HEADS) {
        int i = t / HEADS, m = t % HEADS;
        float s = 0.f;
#pragma unroll
        for (int j = 0; j < HEADS; j++)
            s += (-0.5f * theta[i * HEADS + j]) * w[j * HEADS + m];
        g_M[t] = s;
    }
}

// ---------------- QKV: [2048,768] @ Wqkv^T[768,2304], scatter to heads -----
__global__ __launch_bounds__(256, 2) void qkv_tc(const float* __restrict__ W) {
    extern __shared__ float dynsm[];
    float* As = dynsm;
    float* Bs = dynsm + 2 * 128 * PADC;
    int nb = blockIdx.x, mb = blockIdx.y;
    float Cacc[64] = {};
    gemm_pipe<128>(Cacc, g_xn + (size_t)mb * 128 * DIM, DIM,
                   W + (size_t)nb * 128 * DIM, DIM, DIM, As, Bs);

    const int lane = threadIdx.x & 31, wid = threadIdx.x >> 5;
    const int g = lane >> 2, t = lane & 3;
    const int wr = wid >> 2, wc = wid & 3;
#pragma unroll
    for (int mi = 0; mi < 4; mi++) {
        int gi0 = mb * 128 + wr * 64 + mi * 16 + g;
#pragma unroll
        for (int ni = 0; ni < 4; ni++) {
            int j = nb * 128 + wc * 32 + ni * 8 + 2 * t;
            int which = j / INNER;
            int rc = j - which * INNER;
            int h = rc >> 6, d = rc & 63;
            const float* cp = &Cacc[(mi * 4 + ni) * 4];
#pragma unroll
            for (int half = 0; half < 2; half++) {
                int gi = gi0 + half * 8;
                int b = gi >> 10, n = gi & 1023;
                float c0 = cp[half * 2], c1 = cp[half * 2 + 1];
                if (which < 2) {
                    float* dst = (which == 0) ? g_q : g_k;
                    *(float2*)(dst + ((size_t)(b * HEADS + h) * SEQ + n) * DH + d)
                        = make_float2(c0, c1);
                } else {
                    float* p = g_vt + (size_t)(b * HEADS + h) * DH * SEQ + n;
                    p[(size_t)d * SEQ] = c0;
                    p[(size_t)(d + 1) * SEQ] = c1;
                }
            }
        }
    }
}

// ---------------- dots: exp(scale * q@k^T), partial row sums ---------------
__global__ __launch_bounds__(256, 2) void dots_tc() {
    extern __shared__ float dynsm[];
    float* As = dynsm;
    float* Bs = dynsm + 2 * 128 * PADC;
    __shared__ float sred[128][4];
    int nb = blockIdx.x, mb = blockIdx.y, bz = blockIdx.z;
    float Cacc[64] = {};
    gemm_pipe<128>(Cacc, g_q + (size_t)bz * SEQ * DH + (size_t)mb * 128 * DH, DH,
                   g_k + (size_t)bz * SEQ * DH + (size_t)nb * 128 * DH, DH, DH, As, Bs);

    const int lane = threadIdx.x & 31, wid = threadIdx.x >> 5;
    const int g = lane >> 2, t = lane & 3;
    const int wr = wid >> 2, wc = wid & 3;
    float rs0[4] = {}, rs1[4] = {};
#pragma unroll
    for (int mi = 0; mi < 4; mi++) {
        int row0 = mb * 128 + wr * 64 + mi * 16 + g;
#pragma unroll
        for (int ni = 0; ni < 4; ni++) {
            int col = nb * 128 + wc * 32 + ni * 8 + 2 * t;
            float* cp = &Cacc[(mi * 4 + ni) * 4];
            float e0 = __expf(cp[0] * SCALE), e1 = __expf(cp[1] * SCALE);
            float e2 = __expf(cp[2] * SCALE), e3 = __expf(cp[3] * SCALE);
            rs0[mi] += e0 + e1; rs1[mi] += e2 + e3;
            *(float2*)(g_attn + (size_t)bz * NN + (size_t)row0 * SEQ + col)
                = make_float2(e0, e1);
            *(float2*)(g_attn + (size_t)bz * NN + (size_t)(row0 + 8) * SEQ + col)
                = make_float2(e2, e3);
        }
    }
#pragma unroll
    for (int mi = 0; mi < 4; mi++) {
#pragma unroll
        for (int o = 1; o < 4; o <<= 1) {
            rs0[mi] += __shfl_xor_sync(0xffffffffu, rs0[mi], o);
            rs1[mi] += __shfl_xor_sync(0xffffffffu, rs1[mi], o);
        }
        if (t == 0) {
            int rl = wr * 64 + mi * 16 + g;
            sred[rl][wc] = rs0[mi];
            sred[rl + 8][wc] = rs1[mi];
        }
    }
    __syncthreads();
    if (threadIdx.x < 128) {
        float s = sred[threadIdx.x][0] + sred[threadIdx.x][1]
                + sred[threadIdx.x][2] + sred[threadIdx.x][3];
        g_psum[((size_t)bz * SEQ + mb * 128 + threadIdx.x) * 8 + nb] = s;
    }
}

// ---------------- head-mix: P = a + relu(M @ a), a normalized --------------
__global__ __launch_bounds__(256) void mix_kernel() {
    __shared__ float Ms[HEADS * HEADS];
    __shared__ float ri[HEADS];
    int t = blockIdx.x * 256 + threadIdx.x;
    int b = t >> 20;
    int pos = t & (NN - 1);
    int row = pos >> 10;
    if (threadIdx.x < HEADS * HEADS) Ms[threadIdx.x] = g_M[threadIdx.x];
    if (threadIdx.x < HEADS) {
        const float* ps = g_psum + ((size_t)(b * HEADS + threadIdx.x) * SEQ + row) * 8;
        float s = 0.f;
#pragma unroll
        for (int i = 0; i < 8; i++) s += ps[i];
        ri[threadIdx.x] = 1.f / s;
    }
    __syncthreads();
    float a[HEADS];
#pragma unroll
    for (int j = 0; j < HEADS; j++)
        a[j] = g_attn[(size_t)(b * HEADS + j) * NN + pos] * ri[j];
#pragma unroll
    for (int h = 0; h < HEADS; h++) {
        float s = 0.f;
#pragma unroll
        for (int j = 0; j < HEADS; j++) s += Ms[h * HEADS + j] * a[j];
        g_P[(size_t)(b * HEADS + h) * NN + pos] = a[h] + fmaxf(s, 0.f);
    }
}

// ---------------- AV: O[n,d] = P[n,:] @ Vt[d,:]^T --------------------------
__global__ __launch_bounds__(256, 2) void av_tc() {
    extern __shared__ float dynsm[];
    float* As = dynsm;
    float* Bs = dynsm + 2 * 128 * PADC;
    int mb = blockIdx.x, bz = blockIdx.y;
    float Cacc[32] = {};
    gemm_pipe<64>(Cacc, g_P + (size_t)bz * NN + (size_t)mb * 128 * SEQ, SEQ,
                  g_vt + (size_t)bz * DH * SEQ, SEQ, SEQ, As, Bs);

    const int lane = threadIdx.x & 31, wid = threadIdx.x >> 5;
    const int g = lane >> 2, t = lane & 3;
    const int wr = wid >> 1, wc = wid & 1;
    int b = bz / HEADS, h = bz % HEADS;
#pragma unroll
    for (int mi = 0; mi < 2; mi++) {
        int n0 = mb * 128 + wr * 32 + mi * 16 + g;
#pragma unroll
        for (int ni = 0; ni < 4; ni++) {
            int d = wc * 32 + ni * 8 + 2 * t;
            float* cp = &Cacc[(mi * 4 + ni) * 4];
            *(float2*)(g_O + (size_t)(b * SEQ + n0) * INNER + h * DH + d)
                = make_float2(cp[0], cp[1]);
            *(float2*)(g_O + (size_t)(b * SEQ + n0 + 8) * INNER + h * DH + d)
                = make_float2(cp[2], cp[3]);
        }
    }
}

// ---------------- out projection -------------------------------------------
__global__ __launch_bounds__(256, 2) void proj_tc(const float* __restrict__ W,
                                                  const float* __restrict__ bias,
                                                  float* __restrict__ out) {
    extern __shared__ float dynsm[];
    float* As = dynsm;
    float* Bs = dynsm + 2 * 128 * PADC;
    int nb = blockIdx.x, mb = blockIdx.y;
    float Cacc[64] = {};
    gemm_pipe<128>(Cacc, g_O + (size_t)mb * 128 * INNER, INNER,
                   W + (size_t)nb * 128 * INNER, INNER, INNER, As, Bs);

    const int lane = threadIdx.x & 31, wid = threadIdx.x >> 5;
    const int g = lane >> 2, t = lane & 3;
    const int wr = wid >> 2, wc = wid & 3;
#pragma unroll
    for (int mi = 0; mi < 4; mi++) {
        int gi = mb * 128 + wr * 64 + mi * 16 + g;
#pragma unroll
        for (int ni = 0; ni < 4; ni++) {
            int j = nb * 128 + wc * 32 + ni * 8 + 2 * t;
            float b0 = bias[j], b1 = bias[j + 1];
            float* cp = &Cacc[(mi * 4 + ni) * 4];
            *(float2*)(out + (size_t)gi * DIM + j) = make_float2(cp[0] + b0, cp[1] + b1);
            *(float2*)(out + (size_t)(gi + 8) * DIM + j) = make_float2(cp[2] + b0, cp[3] + b1);
        }
    }
}

// ---------------- launcher -------------------------------------------------
extern "C" void kernel_launch(void* const* d_in, const int* in_sizes, int n_in,
                              void* d_out, int out_size) {
    const float* x     = (const float*)d_in[0];
    const float* ln_g  = (const float*)d_in[1];
    const float* ln_b  = (const float*)d_in[2];
    const float* w_qkv = (const float*)d_in[3];
    const float* w_out = (const float*)d_in[4];
    const float* b_out = (const float*)d_in[5];
    const float* theta = (const float*)d_in[6];
    const float* gnn_w = (const float*)d_in[7];
    float* out = (float*)d_out;

    cudaFuncSetAttribute(qkv_tc,  cudaFuncAttributeMaxDynamicSharedMemorySize, SMEM128);
    cudaFuncSetAttribute(dots_tc, cudaFuncAttributeMaxDynamicSharedMemorySize, SMEM128);
    cudaFuncSetAttribute(av_tc,   cudaFuncAttributeMaxDynamicSharedMemorySize, SMEM64);
    cudaFuncSetAttribute(proj_tc, cudaFuncAttributeMaxDynamicSharedMemorySize, SMEM128);

    ln_kernel<<<ROWS, 256>>>(x, ln_g, ln_b);
    m_kernel<<<1, 160>>>(theta, gnn_w);
    qkv_tc<<<dim3(18, 16), 256, SMEM128>>>(w_qkv);
    dots_tc<<<dim3(8, 8, BH), 256, SMEM128>>>();
    mix_kernel<<<(BATCH * NN) / 256, 256>>>();
    av_tc<<<dim3(8, BH), 256, SMEM64>>>();
    proj_tc<<<dim3(6, 16), 256, SMEM128>>>(w_out, b_out, out);
}

// round 10
// speedup vs baseline: 2.4633x; 1.0488x over previous
#include <cuda_runtime.h>
#include <cstdint>

#define DIM 768
#define HEADS 12
#define DH 64
#define INNER 768
#define BATCH 2
#define SEQ 1024
#define ROWS (BATCH*SEQ)      // 2048
#define NN (SEQ*SEQ)          // 1048576
#define BH (BATCH*HEADS)      // 24
#define SCALE 0.125f
#define LN_EPS 1e-5f
#define PADC 36               // floats per 32-float chunk row (144B, 16B mult)
#define NSPLIT 2
#define NB_PER (8/NSPLIT)     // k-tiles per dots block

// ---------------- scratch (device globals; no allocation allowed) ----------
__device__ float g_xn[ROWS*DIM];
__device__ float g_q[BH*SEQ*DH];
__device__ float g_k[BH*SEQ*DH];
__device__ float g_vt[BH*DH*SEQ];              // V transposed: [bh][d][n]
__device__ float g_attn[(size_t)BH*NN];        // exp(logits), unnormalized
__device__ float g_P[(size_t)BH*NN];
__device__ float g_psum[BH*SEQ*NSPLIT];
__device__ float g_O[ROWS*INNER];
__device__ float g_M[HEADS*HEADS];

// ---------------- helpers --------------------------------------------------
__device__ __forceinline__ uint32_t smem_u32(const void* p) {
    uint32_t a;
    asm("{ .reg .u64 t; cvta.to.shared.u64 t, %1; cvt.u32.u64 %0, t; }"
        : "=r"(a) : "l"(p));
    return a;
}
__device__ __forceinline__ float to_tf32(float x) {
    float y;
    asm("cvt.rna.tf32.f32 %0, %1;" : "=f"(y) : "f"(x));
    return y;
}
__device__ __forceinline__ void mma_tf32(float* c, const uint32_t* a, const uint32_t* b) {
    asm volatile(
        "mma.sync.aligned.m16n8k8.row.col.f32.tf32.tf32.f32 "
        "{%0,%1,%2,%3}, {%4,%5,%6,%7}, {%8,%9}, {%0,%1,%2,%3};"
        : "+f"(c[0]), "+f"(c[1]), "+f"(c[2]), "+f"(c[3])
        : "r"(a[0]), "r"(a[1]), "r"(a[2]), "r"(a[3]), "r"(b[0]), "r"(b[1]));
}
#define CP_ASYNC16(dst, src) \
    asm volatile("cp.async.cg.shared.global [%0], [%1], 16;" \
        :: "r"(dst), "l"(src) : "memory")
#define CP_COMMIT()  asm volatile("cp.async.commit_group;" ::: "memory")
#define CP_WAIT1()   asm volatile("cp.async.wait_group 1;" ::: "memory")
#define CP_WAIT0()   asm volatile("cp.async.wait_group 0;" ::: "memory")

// ---- pipelined tf32 mma core (qkv/av/proj): D[128,BN]=A[128,K]@B[BN,K]^T --
template<int BN>
__device__ __forceinline__ void gemm_pipe(float* Cacc,
                                          const float* __restrict__ A, int lda,
                                          const float* __restrict__ B, int ldb,
                                          int K, float* As, float* Bs) {
    constexpr int WC = BN / 32;
    constexpr int WR = 8 / WC;
    constexpr int WM = 128 / WR;
    constexpr int MT = WM / 16;
    constexpr int BTPR = 256 / BN;
    constexpr int BSEG = 32 / BTPR;

    const int tid = threadIdx.x, wid = tid >> 5, lane = tid & 31;
    const int g = lane >> 2, t = lane & 3;
    const int wr = wid / WC, wc = wid % WC;
    const int wm0 = wr * WM, wn0 = wc * 32;
    const int arow = tid >> 1, ac0 = (tid & 1) * 16;
    const int brow = tid / BTPR, bc0 = (tid % BTPR) * BSEG;

    const uint32_t sa = smem_u32(As);
    const uint32_t sb = smem_u32(Bs);
    const int nch = K >> 5;

    auto prefetch = [&](int c, int buf) {
        const float* ap = A + (size_t)arow * lda + c * 32 + ac0;
        uint32_t da = sa + (uint32_t)(buf * 128 * PADC + arow * PADC + ac0) * 4u;
#pragma unroll
        for (int i = 0; i < 4; i++) CP_ASYNC16(da + i * 16, ap + i * 4);
        const float* bp = B + (size_t)brow * ldb + c * 32 + bc0;
        uint32_t db = sb + (uint32_t)(buf * BN * PADC + brow * PADC + bc0) * 4u;
#pragma unroll
        for (int i = 0; i < BSEG / 4; i++) CP_ASYNC16(db + i * 16, bp + i * 4);
        CP_COMMIT();
    };

    prefetch(0, 0);
    for (int c = 0; c < nch; c++) {
        if (c + 1 < nch) { prefetch(c + 1, (c + 1) & 1); CP_WAIT1(); }
        else             { CP_WAIT0(); }
        __syncthreads();
        const float* Ab = As + (c & 1) * 128 * PADC;
        const float* Bb = Bs + (c & 1) * BN * PADC;
#pragma unroll
        for (int ks = 0; ks < 4; ks++) {
            const int kk = ks * 8 + t;
            uint32_t af[MT][4], bf[4][2];
#pragma unroll
            for (int mi = 0; mi < MT; mi++) {
                int r = wm0 + mi * 16 + g;
                af[mi][0] = __float_as_uint(to_tf32(Ab[r * PADC + kk]));
                af[mi][1] = __float_as_uint(to_tf32(Ab[(r + 8) * PADC + kk]));
                af[mi][2] = __float_as_uint(to_tf32(Ab[r * PADC + kk + 4]));
                af[mi][3] = __float_as_uint(to_tf32(Ab[(r + 8) * PADC + kk + 4]));
            }
#pragma unroll
            for (int ni = 0; ni < 4; ni++) {
                int r = wn0 + ni * 8 + g;
                bf[ni][0] = __float_as_uint(to_tf32(Bb[r * PADC + kk]));
                bf[ni][1] = __float_as_uint(to_tf32(Bb[r * PADC + kk + 4]));
            }
#pragma unroll
            for (int mi = 0; mi < MT; mi++)
#pragma unroll
                for (int ni = 0; ni < 4; ni++)
                    mma_tf32(&Cacc[(mi * 4 + ni) * 4], af[mi], bf[ni]);
        }
        __syncthreads();
    }
}

#define SMEM128 ((2*128 + 2*128) * PADC * 4)   // 73728 B
#define SMEM64  ((2*128 + 2*64)  * PADC * 4)   // 55296 B

// ---------------- LayerNorm ------------------------------------------------
__global__ __launch_bounds__(256) void ln_kernel(const float* __restrict__ x,
                                                 const float* __restrict__ gam,
                                                 const float* __restrict__ bet) {
    int row = blockIdx.x;
    const float* xr = x + (size_t)row * DIM;
    float vals[3];
    float s = 0.f, s2 = 0.f;
#pragma unroll
    for (int i = 0; i < 3; i++) {
        float v = xr[threadIdx.x + i * 256];
        vals[i] = v; s += v; s2 += v * v;
    }
    __shared__ float sh1[32], sh2[32];
#pragma unroll
    for (int o = 16; o > 0; o >>= 1) {
        s  += __shfl_down_sync(0xffffffffu, s,  o);
        s2 += __shfl_down_sync(0xffffffffu, s2, o);
    }
    int lane = threadIdx.x & 31, wid = threadIdx.x >> 5;
    if (lane == 0) { sh1[wid] = s; sh2[wid] = s2; }
    __syncthreads();
    if (wid == 0) {
        s  = (lane < 8) ? sh1[lane] : 0.f;
        s2 = (lane < 8) ? sh2[lane] : 0.f;
#pragma unroll
        for (int o = 4; o > 0; o >>= 1) {
            s  += __shfl_down_sync(0xffffffffu, s,  o);
            s2 += __shfl_down_sync(0xffffffffu, s2, o);
        }
        if (lane == 0) { sh1[0] = s; sh2[0] = s2; }
    }
    __syncthreads();
    float mean = sh1[0] * (1.f / DIM);
    float var  = sh2[0] * (1.f / DIM) - mean * mean;
    float rstd = rsqrtf(var + LN_EPS);
#pragma unroll
    for (int i = 0; i < 3; i++) {
        int c = threadIdx.x + i * 256;
        g_xn[(size_t)row * DIM + c] = (vals[i] - mean) * rstd * gam[c] + bet[c];
    }
}

// ---------------- M = (-0.5*theta) @ gnn_w ---------------------------------
__global__ void m_kernel(const float* __restrict__ theta, const float* __restrict__ w) {
    int t = threadIdx.x;
    if (t < HEADS * HEADS) {
        int i = t / HEADS, m = t % HEADS;
        float s = 0.f;
#pragma unroll
        for (int j = 0; j < HEADS; j++)
            s += (-0.5f * theta[i * HEADS + j]) * w[j * HEADS + m];
        g_M[t] = s;
    }
}

// ---------------- QKV: [2048,768] @ Wqkv^T[768,2304], scatter to heads -----
__global__ __launch_bounds__(256, 2) void qkv_tc(const float* __restrict__ W) {
    extern __shared__ float dynsm[];
    float* As = dynsm;
    float* Bs = dynsm + 2 * 128 * PADC;
    int nb = blockIdx.x, mb = blockIdx.y;
    float Cacc[64] = {};
    gemm_pipe<128>(Cacc, g_xn + (size_t)mb * 128 * DIM, DIM,
                   W + (size_t)nb * 128 * DIM, DIM, DIM, As, Bs);

    const int lane = threadIdx.x & 31, wid = threadIdx.x >> 5;
    const int g = lane >> 2, t = lane & 3;
    const int wr = wid >> 2, wc = wid & 3;
#pragma unroll
    for (int mi = 0; mi < 4; mi++) {
        int gi0 = mb * 128 + wr * 64 + mi * 16 + g;
#pragma unroll
        for (int ni = 0; ni < 4; ni++) {
            int j = nb * 128 + wc * 32 + ni * 8 + 2 * t;
            int which = j / INNER;
            int rc = j - which * INNER;
            int h = rc >> 6, d = rc & 63;
            const float* cp = &Cacc[(mi * 4 + ni) * 4];
#pragma unroll
            for (int half = 0; half < 2; half++) {
                int gi = gi0 + half * 8;
                int b = gi >> 10, n = gi & 1023;
                float c0 = cp[half * 2], c1 = cp[half * 2 + 1];
                if (which < 2) {
                    float* dst = (which == 0) ? g_q : g_k;
                    *(float2*)(dst + ((size_t)(b * HEADS + h) * SEQ + n) * DH + d)
                        = make_float2(c0, c1);
                } else {
                    float* p = g_vt + (size_t)(b * HEADS + h) * DH * SEQ + n;
                    p[(size_t)d * SEQ] = c0;
                    p[(size_t)(d + 1) * SEQ] = c1;
                }
            }
        }
    }
}

// ---------------- dots strip: q resident, loop over 4 k-tiles --------------
// grid (NSPLIT, 8 mb, 24 bh). Chunk-granular cp.async pipeline (8 chunks).
__global__ __launch_bounds__(256, 2) void dots_tc() {
    extern __shared__ float dynsm[];
    float* As = dynsm;                     // [2 chunks][128][PADC]  (q, resident)
    float* Bs = dynsm + 2 * 128 * PADC;    // [2 bufs][128][PADC]    (k, pipelined)
    __shared__ float sred[128][4];
    const int split = blockIdx.x, mb = blockIdx.y, bz = blockIdx.z;
    const float* Aq = g_q + (size_t)bz * SEQ * DH + (size_t)mb * 128 * DH;
    const float* Bk = g_k + (size_t)bz * SEQ * DH;

    const int tid = threadIdx.x, wid = tid >> 5, lane = tid & 31;
    const int g = lane >> 2, t = lane & 3;
    const int wr = wid >> 2, wc = wid & 3;
    const int arow = tid >> 1, ac0 = (tid & 1) * 16;
    const uint32_t sa = smem_u32(As);
    const uint32_t sb = smem_u32(Bs);

    // load q (both chunks) once — group 0
#pragma unroll
    for (int ch = 0; ch < 2; ch++) {
        const float* ap = Aq + (size_t)arow * DH + ch * 32 + ac0;
        uint32_t da = sa + (uint32_t)(ch * 128 * PADC + arow * PADC + ac0) * 4u;
#pragma unroll
        for (int i = 0; i < 4; i++) CP_ASYNC16(da + i * 16, ap + i * 4);
    }
    CP_COMMIT();

    auto prefetch_k = [&](int gc, int buf) {
        int nb = split * NB_PER + (gc >> 1);
        int ch = gc & 1;
        const float* bp = Bk + ((size_t)nb * 128 + arow) * DH + ch * 32 + ac0;
        uint32_t db = sb + (uint32_t)(buf * 128 * PADC + arow * PADC + ac0) * 4u;
#pragma unroll
        for (int i = 0; i < 4; i++) CP_ASYNC16(db + i * 16, bp + i * 4);
        CP_COMMIT();
    };

    prefetch_k(0, 0);                       // group 1
    const int NCH = NB_PER * 2;
    float rs0[4] = {}, rs1[4] = {};
    float Cacc[64];
    for (int gc = 0; gc < NCH; gc++) {
        if (gc + 1 < NCH) { prefetch_k(gc + 1, (gc + 1) & 1); CP_WAIT1(); }
        else              { CP_WAIT0(); }
        __syncthreads();
        if ((gc & 1) == 0) {
#pragma unroll
            for (int i = 0; i < 64; i++) Cacc[i] = 0.f;
        }
        const float* Ab = As + (gc & 1) * 128 * PADC;
        const float* Bb = Bs + (gc & 1) * 128 * PADC;
#pragma unroll
        for (int ks = 0; ks < 4; ks++) {
            const int kk = ks * 8 + t;
            uint32_t af[4][4], bf[4][2];
#pragma unroll
            for (int mi = 0; mi < 4; mi++) {
                int r = wr * 64 + mi * 16 + g;
                af[mi][0] = __float_as_uint(to_tf32(Ab[r * PADC + kk]));
                af[mi][1] = __float_as_uint(to_tf32(Ab[(r + 8) * PADC + kk]));
                af[mi][2] = __float_as_uint(to_tf32(Ab[r * PADC + kk + 4]));
                af[mi][3] = __float_as_uint(to_tf32(Ab[(r + 8) * PADC + kk + 4]));
            }
#pragma unroll
            for (int ni = 0; ni < 4; ni++) {
                int r = wc * 32 + ni * 8 + g;
                bf[ni][0] = __float_as_uint(to_tf32(Bb[r * PADC + kk]));
                bf[ni][1] = __float_as_uint(to_tf32(Bb[r * PADC + kk + 4]));
            }
#pragma unroll
            for (int mi = 0; mi < 4; mi++)
#pragma unroll
                for (int ni = 0; ni < 4; ni++)
                    mma_tf32(&Cacc[(mi * 4 + ni) * 4], af[mi], bf[ni]);
        }
        __syncthreads();
        if ((gc & 1) == 1) {
            int nb = split * NB_PER + (gc >> 1);
#pragma unroll
            for (int mi = 0; mi < 4; mi++) {
                int row0 = mb * 128 + wr * 64 + mi * 16 + g;
#pragma unroll
                for (int ni = 0; ni < 4; ni++) {
                    int col = nb * 128 + wc * 32 + ni * 8 + 2 * t;
                    float* cp = &Cacc[(mi * 4 + ni) * 4];
                    float e0 = __expf(cp[0] * SCALE), e1 = __expf(cp[1] * SCALE);
                    float e2 = __expf(cp[2] * SCALE), e3 = __expf(cp[3] * SCALE);
                    rs0[mi] += e0 + e1; rs1[mi] += e2 + e3;
                    *(float2*)(g_attn + (size_t)bz * NN + (size_t)row0 * SEQ + col)
                        = make_float2(e0, e1);
                    *(float2*)(g_attn + (size_t)bz * NN + (size_t)(row0 + 8) * SEQ + col)
                        = make_float2(e2, e3);
                }
            }
        }
    }
#pragma unroll
    for (int mi = 0; mi < 4; mi++) {
#pragma unroll
        for (int o = 1; o < 4; o <<= 1) {
            rs0[mi] += __shfl_xor_sync(0xffffffffu, rs0[mi], o);
            rs1[mi] += __shfl_xor_sync(0xffffffffu, rs1[mi], o);
        }
        if (t == 0) {
            int rl = wr * 64 + mi * 16 + g;
            sred[rl][wc] = rs0[mi];
            sred[rl + 8][wc] = rs1[mi];
        }
    }
    __syncthreads();
    if (tid < 128) {
        float s = sred[tid][0] + sred[tid][1] + sred[tid][2] + sred[tid][3];
        g_psum[((size_t)bz * SEQ + mb * 128 + tid) * NSPLIT + split] = s;
    }
}

// ---------------- head-mix (float4): one block == one (batch,row) ----------
__global__ __launch_bounds__(256) void mix_kernel() {
    __shared__ float Ms[HEADS * HEADS];
    __shared__ float ri[HEADS];
    const int blk = blockIdx.x;           // 0..ROWS-1
    const int b = blk >> 10;
    const int row = blk & 1023;
    const int tid = threadIdx.x;
    if (tid < HEADS * HEADS) Ms[tid] = g_M[tid];
    if (tid < HEADS) {
        const float* ps = g_psum + ((size_t)(b * HEADS + tid) * SEQ + row) * NSPLIT;
        float s = 0.f;
#pragma unroll
        for (int i = 0; i < NSPLIT; i++) s += ps[i];
        ri[tid] = 1.f / s;
    }
    __syncthreads();
    const size_t base = (size_t)b * HEADS * NN + (size_t)row * SEQ + tid * 4;
    float4 a[HEADS];
#pragma unroll
    for (int j = 0; j < HEADS; j++) {
        float4 v = *(const float4*)(g_attn + base + (size_t)j * NN);
        float r = ri[j];
        a[j] = make_float4(v.x * r, v.y * r, v.z * r, v.w * r);
    }
#pragma unroll
    for (int h = 0; h < HEADS; h++) {
        float4 s = make_float4(0.f, 0.f, 0.f, 0.f);
#pragma unroll
        for (int j = 0; j < HEADS; j++) {
            float m = Ms[h * HEADS + j];
            s.x += m * a[j].x; s.y += m * a[j].y;
            s.z += m * a[j].z; s.w += m * a[j].w;
        }
        float4 o = make_float4(a[h].x + fmaxf(s.x, 0.f), a[h].y + fmaxf(s.y, 0.f),
                               a[h].z + fmaxf(s.z, 0.f), a[h].w + fmaxf(s.w, 0.f));
        *(float4*)(g_P + base + (size_t)h * NN) = o;
    }
}

// ---------------- AV: O[n,d] = P[n,:] @ Vt[d,:]^T --------------------------
__global__ __launch_bounds__(256, 2) void av_tc() {
    extern __shared__ float dynsm[];
    float* As = dynsm;
    float* Bs = dynsm + 2 * 128 * PADC;
    int mb = blockIdx.x, bz = blockIdx.y;
    float Cacc[32] = {};
    gemm_pipe<64>(Cacc, g_P + (size_t)bz * NN + (size_t)mb * 128 * SEQ, SEQ,
                  g_vt + (size_t)bz * DH * SEQ, SEQ, SEQ, As, Bs);

    const int lane = threadIdx.x & 31, wid = threadIdx.x >> 5;
    const int g = lane >> 2, t = lane & 3;
    const int wr = wid >> 1, wc = wid & 1;
    int b = bz / HEADS, h = bz % HEADS;
#pragma unroll
    for (int mi = 0; mi < 2; mi++) {
        int n0 = mb * 128 + wr * 32 + mi * 16 + g;
#pragma unroll
        for (int ni = 0; ni < 4; ni++) {
            int d = wc * 32 + ni * 8 + 2 * t;
            float* cp = &Cacc[(mi * 4 + ni) * 4];
            *(float2*)(g_O + (size_t)(b * SEQ + n0) * INNER + h * DH + d)
                = make_float2(cp[0], cp[1]);
            *(float2*)(g_O + (size_t)(b * SEQ + n0 + 8) * INNER + h * DH + d)
                = make_float2(cp[2], cp[3]);
        }
    }
}

// ---------------- out projection -------------------------------------------
__global__ __launch_bounds__(256, 2) void proj_tc(const float* __restrict__ W,
                                                  const float* __restrict__ bias,
                                                  float* __restrict__ out) {
    extern __shared__ float dynsm[];
    float* As = dynsm;
    float* Bs = dynsm + 2 * 128 * PADC;
    int nb = blockIdx.x, mb = blockIdx.y;
    float Cacc[64] = {};
    gemm_pipe<128>(Cacc, g_O + (size_t)mb * 128 * INNER, INNER,
                   W + (size_t)nb * 128 * INNER, INNER, INNER, As, Bs);

    const int lane = threadIdx.x & 31, wid = threadIdx.x >> 5;
    const int g = lane >> 2, t = lane & 3;
    const int wr = wid >> 2, wc = wid & 3;
#pragma unroll
    for (int mi = 0; mi < 4; mi++) {
        int gi = mb * 128 + wr * 64 + mi * 16 + g;
#pragma unroll
        for (int ni = 0; ni < 4; ni++) {
            int j = nb * 128 + wc * 32 + ni * 8 + 2 * t;
            float b0 = bias[j], b1 = bias[j + 1];
            float* cp = &Cacc[(mi * 4 + ni) * 4];
            *(float2*)(out + (size_t)gi * DIM + j) = make_float2(cp[0] + b0, cp[1] + b1);
            *(float2*)(out + (size_t)(gi + 8) * DIM + j) = make_float2(cp[2] + b0, cp[3] + b1);
        }
    }
}

// ---------------- launcher -------------------------------------------------
extern "C" void kernel_launch(void* const* d_in, const int* in_sizes, int n_in,
                              void* d_out, int out_size) {
    const float* x     = (const float*)d_in[0];
    const float* ln_g  = (const float*)d_in[1];
    const float* ln_b  = (const float*)d_in[2];
    const float* w_qkv = (const float*)d_in[3];
    const float* w_out = (const float*)d_in[4];
    const float* b_out = (const float*)d_in[5];
    const float* theta = (const float*)d_in[6];
    const float* gnn_w = (const float*)d_in[7];
    float* out = (float*)d_out;

    cudaFuncSetAttribute(qkv_tc,  cudaFuncAttributeMaxDynamicSharedMemorySize, SMEM128);
    cudaFuncSetAttribute(dots_tc, cudaFuncAttributeMaxDynamicSharedMemorySize, SMEM128);
    cudaFuncSetAttribute(av_tc,   cudaFuncAttributeMaxDynamicSharedMemorySize, SMEM64);
    cudaFuncSetAttribute(proj_tc, cudaFuncAttributeMaxDynamicSharedMemorySize, SMEM128);

    ln_kernel<<<ROWS, 256>>>(x, ln_g, ln_b);
    m_kernel<<<1, 160>>>(theta, gnn_w);
    qkv_tc<<<dim3(18, 16), 256, SMEM128>>>(w_qkv);
    dots_tc<<<dim3(NSPLIT, 8, BH), 256, SMEM128>>>();
    mix_kernel<<<BATCH * SEQ, 256>>>();   // one block per (batch,row) — FIXED grid
    av_tc<<<dim3(8, BH), 256, SMEM64>>>();
    proj_tc<<<dim3(6, 16), 256, SMEM128>>>(w_out, b_out, out);
}